// round 9
// baseline (speedup 1.0000x reference)
#include <cuda_runtime.h>
#include <cuda_fp16.h>

#define N_NODES 100000
#define N_EDGES 6400000
#define IN_DIM  128
#define HID     16
#define CLASSES 40
#define STRIDE  160

#define CNT_SHIFT 44
#define FIX_SCALE 1048576.0f          // 2^20
#define FIX_MASK  ((1ULL << CNT_SHIFT) - 1ULL)

// ---- scratch (device globals) ----
__device__ int                g_is64;
__device__ unsigned long long g_cd[N_NODES];        // count<<44 | fixpt weighted degree
__device__ int2               g_edge[(size_t)N_NODES * STRIDE];  // (src, w) by dst
__device__ __half2            g_hh[N_NODES * (HID/2)];  // hs = dinv*(x@W), fp16 pairs
__device__ float              g_x[N_NODES * HID];       // aggregation result (fp32)

__device__ __forceinline__ float unpack_dinv(unsigned long long p) {
    float deg = 1.0f + (float)(p & FIX_MASK) * (1.0f / FIX_SCALE); // +1 self loop
    return rsqrtf(deg);
}

// ---------------- probe dtype + zero counters (one launch) ----------------
__global__ void __launch_bounds__(256) init_k(const void* ei) {
    int i = blockIdx.x * blockDim.x + threadIdx.x;
    if (i < N_NODES) g_cd[i] = 0ULL;
    if (blockIdx.x == 0) {
        const long long* p = (const long long*)ei;
        int t = threadIdx.x;
        int bad = 0;
        #pragma unroll
        for (int k = 0; k < 4; k++) {
            int s = t + k * 256;
            long long v = p[((long long)s * 6247) % N_EDGES];
            if (v < 0 || v >= N_NODES) bad = 1;
        }
        int any_bad = __syncthreads_or(bad);
        if (t == 0) g_is64 = any_bad ? 0 : 1;
    }
}

__device__ __forceinline__ int load_ei(const void* ei, long long pos, int is64) {
    return is64 ? (int)((const long long*)ei)[pos] : ((const int*)ei)[pos];
}

// ---------------- fused count+degree+bucket fill ----------------
__global__ void fill_k(const void* __restrict__ ei,
                       const float* __restrict__ w) {
    int e = blockIdx.x * blockDim.x + threadIdx.x;
    if (e >= N_EDGES) return;
    int is64 = g_is64;
    int r = load_ei(ei, e, is64);
    int c = load_ei(ei, (long long)N_EDGES + e, is64);
    float wv = w[e];
    unsigned long long pack = (1ULL << CNT_SHIFT) |
        (unsigned long long)(unsigned int)__float2uint_rn(wv * FIX_SCALE);
    unsigned long long old = atomicAdd(&g_cd[c], pack);
    int slot = (int)(old >> CNT_SHIFT);
    g_edge[(size_t)c * STRIDE + slot] = make_int2(r, __float_as_int(wv));
}

// ---------------- layer 1 GEMM: g_hh = half(dinv * (z @ W1)) ---------------
__global__ void __launch_bounds__(128) gemm1_k(const float* __restrict__ z,
                                               const float* __restrict__ W1) {
    __shared__ float Ws[IN_DIM * HID];
    __shared__ float zt[128][33];

    int tid = threadIdx.x;
    int row0 = blockIdx.x * 128;
    for (int i = tid; i < IN_DIM * HID; i += 128) Ws[i] = W1[i];

    float acc[HID];
    #pragma unroll
    for (int c = 0; c < HID; c++) acc[c] = 0.0f;

    for (int k0 = 0; k0 < IN_DIM; k0 += 32) {
        __syncthreads();
        #pragma unroll
        for (int idx = tid; idx < 128 * 32; idx += 128) {
            int r = idx >> 5, kk = idx & 31;
            int gr = row0 + r;
            zt[r][kk] = (gr < N_NODES) ? z[(size_t)gr * IN_DIM + k0 + kk] : 0.0f;
        }
        __syncthreads();
        #pragma unroll
        for (int kk = 0; kk < 32; kk++) {
            float zv = zt[tid][kk];
            const float* wrow = &Ws[(k0 + kk) * HID];
            #pragma unroll
            for (int c = 0; c < HID; c++) acc[c] = fmaf(zv, wrow[c], acc[c]);
        }
    }
    int row = row0 + tid;
    if (row < N_NODES) {
        float di = unpack_dinv(g_cd[row]);
        __half2 hv[HID/2];
        #pragma unroll
        for (int j = 0; j < HID/2; j++)
            hv[j] = __floats2half2_rn(di * acc[2*j], di * acc[2*j+1]);
        float4* hp = (float4*)(g_hh + (size_t)row * (HID/2));
        hp[0] = *(float4*)&hv[0];
        hp[1] = *(float4*)&hv[4];
    }
}

// ---------------- aggregation: pure gather (fp16 src, fp32 acc) -------------
// 8 lanes per node, each lane owns 2 features (one half2). Block 256 = 32 nodes.
__global__ void __launch_bounds__(256) agg_k() {
    int tid  = threadIdx.x;
    int node = blockIdx.x * 32 + (tid >> 3);
    int lane = tid & 7;
    if (node >= N_NODES) return;

    unsigned long long pk = g_cd[node];
    int end = (int)(pk >> CNT_SHIFT);
    float di = unpack_dinv(pk);

    float2 sv = __half22float2(g_hh[(size_t)node * 8 + lane]);   // self term
    float ax = sv.x, ay = sv.y;

    const int2* bucket = g_edge + (size_t)node * STRIDE;
    int k = 0;
    for (; k + 4 <= end; k += 4) {
        int2 e0 = __ldg(bucket + k + 0);
        int2 e1 = __ldg(bucket + k + 1);
        int2 e2 = __ldg(bucket + k + 2);
        int2 e3 = __ldg(bucket + k + 3);
        float2 h0 = __half22float2(g_hh[(size_t)e0.x * 8 + lane]);
        float2 h1 = __half22float2(g_hh[(size_t)e1.x * 8 + lane]);
        float2 h2 = __half22float2(g_hh[(size_t)e2.x * 8 + lane]);
        float2 h3 = __half22float2(g_hh[(size_t)e3.x * 8 + lane]);
        float w0 = __int_as_float(e0.y), w1 = __int_as_float(e1.y);
        float w2 = __int_as_float(e2.y), w3 = __int_as_float(e3.y);
        ax = fmaf(w0, h0.x, ax); ay = fmaf(w0, h0.y, ay);
        ax = fmaf(w1, h1.x, ax); ay = fmaf(w1, h1.y, ay);
        ax = fmaf(w2, h2.x, ax); ay = fmaf(w2, h2.y, ay);
        ax = fmaf(w3, h3.x, ax); ay = fmaf(w3, h3.y, ay);
    }
    for (; k < end; k++) {
        int2 e = __ldg(bucket + k);
        float2 h = __half22float2(g_hh[(size_t)e.x * 8 + lane]);
        float wv = __int_as_float(e.y);
        ax = fmaf(wv, h.x, ax); ay = fmaf(wv, h.y, ay);
    }
    float2* xp = (float2*)(g_x + (size_t)node * HID + 2 * lane);
    *xp = make_float2(di * ax, di * ay);
}

// ---------------- layer 2: g_hh = half(dinv * (relu(g_x + b1) @ W2)) --------
__global__ void gemm2_k(const float* __restrict__ W2,
                        const float* __restrict__ b1) {
    __shared__ float Ws[HID * HID];
    __shared__ float bs[HID];
    int tid = threadIdx.x;
    if (tid < HID * HID) Ws[tid] = W2[tid];
    if (tid < HID) bs[tid] = b1[tid];
    __syncthreads();

    int i = blockIdx.x * blockDim.x + tid;
    if (i >= N_NODES) return;

    float v[HID];
    const float4* xp = (const float4*)(g_x + (size_t)i * HID);
    #pragma unroll
    for (int j = 0; j < 4; j++) {
        float4 t = xp[j];
        v[j*4+0] = t.x; v[j*4+1] = t.y; v[j*4+2] = t.z; v[j*4+3] = t.w;
    }
    #pragma unroll
    for (int kk = 0; kk < HID; kk++) v[kk] = fmaxf(v[kk] + bs[kk], 0.0f);

    float acc[HID];
    #pragma unroll
    for (int c = 0; c < HID; c++) acc[c] = 0.0f;
    #pragma unroll
    for (int kk = 0; kk < HID; kk++) {
        #pragma unroll
        for (int c = 0; c < HID; c++) acc[c] = fmaf(v[kk], Ws[kk * HID + c], acc[c]);
    }
    float di = unpack_dinv(g_cd[i]);
    __half2 hv[HID/2];
    #pragma unroll
    for (int j = 0; j < HID/2; j++)
        hv[j] = __floats2half2_rn(di * acc[2*j], di * acc[2*j+1]);
    float4* hp = (float4*)(g_hh + (size_t)i * (HID/2));
    hp[0] = *(float4*)&hv[0];
    hp[1] = *(float4*)&hv[4];
}

// ---------------- classifier + bias2 + log_softmax ----------------
__global__ void __launch_bounds__(128) cls_k(const float* __restrict__ b2,
                                             const float* __restrict__ Wc,
                                             const float* __restrict__ bc,
                                             float* __restrict__ out) {
    __shared__ float Ws[HID * CLASSES];
    __shared__ float bcs[CLASSES];
    __shared__ float b2s[HID];
    int tid = threadIdx.x;
    for (int i = tid; i < HID * CLASSES; i += 128) Ws[i] = Wc[i];
    if (tid < CLASSES) bcs[tid] = bc[tid];
    if (tid < HID) b2s[tid] = b2[tid];
    __syncthreads();

    int i = blockIdx.x * 128 + tid;
    if (i >= N_NODES) return;

    float v[HID];
    const float4* xp = (const float4*)(g_x + (size_t)i * HID);
    #pragma unroll
    for (int j = 0; j < 4; j++) {
        float4 t = xp[j];
        v[j*4+0] = t.x; v[j*4+1] = t.y; v[j*4+2] = t.z; v[j*4+3] = t.w;
    }
    #pragma unroll
    for (int kk = 0; kk < HID; kk++) v[kk] += b2s[kk];

    float lg[CLASSES];
    #pragma unroll
    for (int j = 0; j < CLASSES; j++) lg[j] = bcs[j];
    #pragma unroll
    for (int kk = 0; kk < HID; kk++) {
        float vk = v[kk];
        #pragma unroll
        for (int j = 0; j < CLASSES; j++) lg[j] = fmaf(vk, Ws[kk * CLASSES + j], lg[j]);
    }

    float mx = lg[0];
    #pragma unroll
    for (int j = 1; j < CLASSES; j++) mx = fmaxf(mx, lg[j]);
    float se = 0.0f;
    #pragma unroll
    for (int j = 0; j < CLASSES; j++) se += __expf(lg[j] - mx);
    float lse = mx + __logf(se);

    float4* op = (float4*)(out + (size_t)i * CLASSES);
    #pragma unroll
    for (int j = 0; j < CLASSES / 4; j++)
        op[j] = make_float4(lg[j*4+0] - lse, lg[j*4+1] - lse,
                            lg[j*4+2] - lse, lg[j*4+3] - lse);
}

// ---------------- launcher ----------------
extern "C" void kernel_launch(void* const* d_in, const int* in_sizes, int n_in,
                              void* d_out, int out_size) {
    const float* z  = (const float*)d_in[0];
    const void*  ei = d_in[1];
    const float* w  = (const float*)d_in[2];
    const float* W1 = (const float*)d_in[3];
    const float* b1 = (const float*)d_in[4];
    const float* W2 = (const float*)d_in[5];
    const float* b2 = (const float*)d_in[6];
    const float* Wc = (const float*)d_in[7];
    const float* bc = (const float*)d_in[8];
    float* out = (float*)d_out;

    const int TB = 256;
    int nb_n = (N_NODES + TB - 1) / TB;
    int nb_e = (N_EDGES + TB - 1) / TB;
    int nb_g = (N_NODES + 127) / 128;
    int nb_a = (N_NODES + 31) / 32;

    init_k<<<nb_n, TB>>>(ei);
    fill_k<<<nb_e, TB>>>(ei, w);

    gemm1_k<<<nb_g, 128>>>(z, W1);     // dinv + fp16 conversion in epilogue
    agg_k<<<nb_a, 256>>>();

    gemm2_k<<<nb_n, TB>>>(W2, b1);
    agg_k<<<nb_a, 256>>>();

    cls_k<<<nb_g, 128>>>(b2, Wc, bc, out);
}

// round 10
// speedup vs baseline: 1.0008x; 1.0008x over previous
#include <cuda_runtime.h>
#include <cuda_fp16.h>

#define N_NODES 100000
#define N_EDGES 6400000
#define IN_DIM  128
#define HID     16
#define CLASSES 40
#define STRIDE  160

#define CNT_SHIFT 44
#define FIX_SCALE 1048576.0f          // 2^20
#define FIX_MASK  ((1ULL << CNT_SHIFT) - 1ULL)

// ---- scratch (device globals) ----
__device__ int                g_is64;
__device__ unsigned long long g_cd[N_NODES];        // count<<44 | fixpt weighted degree
__device__ int2               g_edge[(size_t)N_NODES * STRIDE];  // (src, w) by dst
__device__ __half2            g_hh[N_NODES * (HID/2)];  // hs = dinv*(x@W), fp16 pairs
__device__ float              g_x[N_NODES * HID];       // aggregation result (fp32)

__device__ __forceinline__ float unpack_dinv(unsigned long long p) {
    float deg = 1.0f + (float)(p & FIX_MASK) * (1.0f / FIX_SCALE); // +1 self loop
    return rsqrtf(deg);
}

// ---------------- probe dtype + zero counters (one launch) ----------------
__global__ void __launch_bounds__(256) init_k(const void* ei) {
    int i = blockIdx.x * blockDim.x + threadIdx.x;
    if (i < N_NODES) g_cd[i] = 0ULL;
    if (blockIdx.x == 0) {
        const long long* p = (const long long*)ei;
        int t = threadIdx.x;
        int bad = 0;
        #pragma unroll
        for (int k = 0; k < 4; k++) {
            int s = t + k * 256;
            long long v = p[((long long)s * 6247) % N_EDGES];
            if (v < 0 || v >= N_NODES) bad = 1;
        }
        int any_bad = __syncthreads_or(bad);
        if (t == 0) g_is64 = any_bad ? 0 : 1;
    }
}

__device__ __forceinline__ int load_ei(const void* ei, long long pos, int is64) {
    return is64 ? (int)((const long long*)ei)[pos] : ((const int*)ei)[pos];
}

// ---------------- fused count+degree+bucket fill ----------------
__global__ void fill_k(const void* __restrict__ ei,
                       const float* __restrict__ w) {
    int e = blockIdx.x * blockDim.x + threadIdx.x;
    if (e >= N_EDGES) return;
    int is64 = g_is64;
    int r = load_ei(ei, e, is64);
    int c = load_ei(ei, (long long)N_EDGES + e, is64);
    float wv = w[e];
    unsigned long long pack = (1ULL << CNT_SHIFT) |
        (unsigned long long)(unsigned int)__float2uint_rn(wv * FIX_SCALE);
    unsigned long long old = atomicAdd(&g_cd[c], pack);
    int slot = (int)(old >> CNT_SHIFT);
    g_edge[(size_t)c * STRIDE + slot] = make_int2(r, __float_as_int(wv));
}

// ---------------- layer 1 GEMM: g_hh = half(dinv * (z @ W1)) ---------------
__global__ void __launch_bounds__(128) gemm1_k(const float* __restrict__ z,
                                               const float* __restrict__ W1) {
    __shared__ float Ws[IN_DIM * HID];
    __shared__ float zt[128][33];

    int tid = threadIdx.x;
    int row0 = blockIdx.x * 128;
    for (int i = tid; i < IN_DIM * HID; i += 128) Ws[i] = W1[i];

    float acc[HID];
    #pragma unroll
    for (int c = 0; c < HID; c++) acc[c] = 0.0f;

    for (int k0 = 0; k0 < IN_DIM; k0 += 32) {
        __syncthreads();
        #pragma unroll
        for (int idx = tid; idx < 128 * 32; idx += 128) {
            int r = idx >> 5, kk = idx & 31;
            int gr = row0 + r;
            zt[r][kk] = (gr < N_NODES) ? z[(size_t)gr * IN_DIM + k0 + kk] : 0.0f;
        }
        __syncthreads();
        #pragma unroll
        for (int kk = 0; kk < 32; kk++) {
            float zv = zt[tid][kk];
            const float* wrow = &Ws[(k0 + kk) * HID];
            #pragma unroll
            for (int c = 0; c < HID; c++) acc[c] = fmaf(zv, wrow[c], acc[c]);
        }
    }
    int row = row0 + tid;
    if (row < N_NODES) {
        float di = unpack_dinv(g_cd[row]);
        __half2 hv[HID/2];
        #pragma unroll
        for (int j = 0; j < HID/2; j++)
            hv[j] = __floats2half2_rn(di * acc[2*j], di * acc[2*j+1]);
        float4* hp = (float4*)(g_hh + (size_t)row * (HID/2));
        hp[0] = *(float4*)&hv[0];
        hp[1] = *(float4*)&hv[4];
    }
}

// ---------------- aggregation: pure gather (fp16 src, fp32 acc) -------------
// 8 lanes per node, each lane owns 2 features (one half2). Block 256 = 32 nodes.
__global__ void __launch_bounds__(256) agg_k() {
    int tid  = threadIdx.x;
    int node = blockIdx.x * 32 + (tid >> 3);
    int lane = tid & 7;
    if (node >= N_NODES) return;

    unsigned long long pk = g_cd[node];
    int end = (int)(pk >> CNT_SHIFT);
    float di = unpack_dinv(pk);

    float2 sv = __half22float2(g_hh[(size_t)node * 8 + lane]);   // self term
    float ax = sv.x, ay = sv.y;

    const int2* bucket = g_edge + (size_t)node * STRIDE;
    int k = 0;
    for (; k + 4 <= end; k += 4) {
        int2 e0 = __ldg(bucket + k + 0);
        int2 e1 = __ldg(bucket + k + 1);
        int2 e2 = __ldg(bucket + k + 2);
        int2 e3 = __ldg(bucket + k + 3);
        float2 h0 = __half22float2(g_hh[(size_t)e0.x * 8 + lane]);
        float2 h1 = __half22float2(g_hh[(size_t)e1.x * 8 + lane]);
        float2 h2 = __half22float2(g_hh[(size_t)e2.x * 8 + lane]);
        float2 h3 = __half22float2(g_hh[(size_t)e3.x * 8 + lane]);
        float w0 = __int_as_float(e0.y), w1 = __int_as_float(e1.y);
        float w2 = __int_as_float(e2.y), w3 = __int_as_float(e3.y);
        ax = fmaf(w0, h0.x, ax); ay = fmaf(w0, h0.y, ay);
        ax = fmaf(w1, h1.x, ax); ay = fmaf(w1, h1.y, ay);
        ax = fmaf(w2, h2.x, ax); ay = fmaf(w2, h2.y, ay);
        ax = fmaf(w3, h3.x, ax); ay = fmaf(w3, h3.y, ay);
    }
    for (; k < end; k++) {
        int2 e = __ldg(bucket + k);
        float2 h = __half22float2(g_hh[(size_t)e.x * 8 + lane]);
        float wv = __int_as_float(e.y);
        ax = fmaf(wv, h.x, ax); ay = fmaf(wv, h.y, ay);
    }
    float2* xp = (float2*)(g_x + (size_t)node * HID + 2 * lane);
    *xp = make_float2(di * ax, di * ay);
}

// ---------------- layer 2: g_hh = half(dinv * (relu(g_x + b1) @ W2)) --------
__global__ void gemm2_k(const float* __restrict__ W2,
                        const float* __restrict__ b1) {
    __shared__ float Ws[HID * HID];
    __shared__ float bs[HID];
    int tid = threadIdx.x;
    if (tid < HID * HID) Ws[tid] = W2[tid];
    if (tid < HID) bs[tid] = b1[tid];
    __syncthreads();

    int i = blockIdx.x * blockDim.x + tid;
    if (i >= N_NODES) return;

    float v[HID];
    const float4* xp = (const float4*)(g_x + (size_t)i * HID);
    #pragma unroll
    for (int j = 0; j < 4; j++) {
        float4 t = xp[j];
        v[j*4+0] = t.x; v[j*4+1] = t.y; v[j*4+2] = t.z; v[j*4+3] = t.w;
    }
    #pragma unroll
    for (int kk = 0; kk < HID; kk++) v[kk] = fmaxf(v[kk] + bs[kk], 0.0f);

    float acc[HID];
    #pragma unroll
    for (int c = 0; c < HID; c++) acc[c] = 0.0f;
    #pragma unroll
    for (int kk = 0; kk < HID; kk++) {
        #pragma unroll
        for (int c = 0; c < HID; c++) acc[c] = fmaf(v[kk], Ws[kk * HID + c], acc[c]);
    }
    float di = unpack_dinv(g_cd[i]);
    __half2 hv[HID/2];
    #pragma unroll
    for (int j = 0; j < HID/2; j++)
        hv[j] = __floats2half2_rn(di * acc[2*j], di * acc[2*j+1]);
    float4* hp = (float4*)(g_hh + (size_t)i * (HID/2));
    hp[0] = *(float4*)&hv[0];
    hp[1] = *(float4*)&hv[4];
}

// ---------------- classifier + bias2 + log_softmax ----------------
__global__ void __launch_bounds__(128) cls_k(const float* __restrict__ b2,
                                             const float* __restrict__ Wc,
                                             const float* __restrict__ bc,
                                             float* __restrict__ out) {
    __shared__ float Ws[HID * CLASSES];
    __shared__ float bcs[CLASSES];
    __shared__ float b2s[HID];
    int tid = threadIdx.x;
    for (int i = tid; i < HID * CLASSES; i += 128) Ws[i] = Wc[i];
    if (tid < CLASSES) bcs[tid] = bc[tid];
    if (tid < HID) b2s[tid] = b2[tid];
    __syncthreads();

    int i = blockIdx.x * 128 + tid;
    if (i >= N_NODES) return;

    float v[HID];
    const float4* xp = (const float4*)(g_x + (size_t)i * HID);
    #pragma unroll
    for (int j = 0; j < 4; j++) {
        float4 t = xp[j];
        v[j*4+0] = t.x; v[j*4+1] = t.y; v[j*4+2] = t.z; v[j*4+3] = t.w;
    }
    #pragma unroll
    for (int kk = 0; kk < HID; kk++) v[kk] += b2s[kk];

    float lg[CLASSES];
    #pragma unroll
    for (int j = 0; j < CLASSES; j++) lg[j] = bcs[j];
    #pragma unroll
    for (int kk = 0; kk < HID; kk++) {
        float vk = v[kk];
        #pragma unroll
        for (int j = 0; j < CLASSES; j++) lg[j] = fmaf(vk, Ws[kk * CLASSES + j], lg[j]);
    }

    float mx = lg[0];
    #pragma unroll
    for (int j = 1; j < CLASSES; j++) mx = fmaxf(mx, lg[j]);
    float se = 0.0f;
    #pragma unroll
    for (int j = 0; j < CLASSES; j++) se += __expf(lg[j] - mx);
    float lse = mx + __logf(se);

    float4* op = (float4*)(out + (size_t)i * CLASSES);
    #pragma unroll
    for (int j = 0; j < CLASSES / 4; j++)
        op[j] = make_float4(lg[j*4+0] - lse, lg[j*4+1] - lse,
                            lg[j*4+2] - lse, lg[j*4+3] - lse);
}

// ---------------- launcher ----------------
extern "C" void kernel_launch(void* const* d_in, const int* in_sizes, int n_in,
                              void* d_out, int out_size) {
    const float* z  = (const float*)d_in[0];
    const void*  ei = d_in[1];
    const float* w  = (const float*)d_in[2];
    const float* W1 = (const float*)d_in[3];
    const float* b1 = (const float*)d_in[4];
    const float* W2 = (const float*)d_in[5];
    const float* b2 = (const float*)d_in[6];
    const float* Wc = (const float*)d_in[7];
    const float* bc = (const float*)d_in[8];
    float* out = (float*)d_out;

    const int TB = 256;
    int nb_n = (N_NODES + TB - 1) / TB;
    int nb_e = (N_EDGES + TB - 1) / TB;
    int nb_g = (N_NODES + 127) / 128;
    int nb_a = (N_NODES + 31) / 32;

    init_k<<<nb_n, TB>>>(ei);
    fill_k<<<nb_e, TB>>>(ei, w);

    gemm1_k<<<nb_g, 128>>>(z, W1);     // dinv + fp16 conversion in epilogue
    agg_k<<<nb_a, 256>>>();

    gemm2_k<<<nb_n, TB>>>(W2, b1);
    agg_k<<<nb_a, 256>>>();

    cls_k<<<nb_g, 128>>>(b2, Wc, bc, out);
}

// round 11
// speedup vs baseline: 1.0087x; 1.0079x over previous
#include <cuda_runtime.h>
#include <cuda_fp16.h>

#define N_NODES 100000
#define N_EDGES 6400000
#define IN_DIM  128
#define HID     16
#define CLASSES 40
#define STRIDE  160

#define CNT_SHIFT 44
#define FIX_SCALE 1048576.0f          // 2^20
#define FIX_MASK  ((1ULL << CNT_SHIFT) - 1ULL)

// ---- scratch (device globals) ----
__device__ int                g_is64;
__device__ unsigned long long g_cd[N_NODES];        // count<<44 | fixpt weighted degree
__device__ int2               g_edge[(size_t)N_NODES * STRIDE];  // (src, w) by dst
__device__ __half2            g_hh[N_NODES * (HID/2)];  // hs = dinv*(x@W), fp16 pairs
__device__ float              g_x[N_NODES * HID];       // aggregation result (fp32)

__device__ __forceinline__ float unpack_dinv(unsigned long long p) {
    float deg = 1.0f + (float)(p & FIX_MASK) * (1.0f / FIX_SCALE); // +1 self loop
    return rsqrtf(deg);
}

// ---------------- probe dtype + zero counters (one launch) ----------------
__global__ void __launch_bounds__(256) init_k(const void* ei) {
    int i = blockIdx.x * blockDim.x + threadIdx.x;
    if (i < N_NODES) g_cd[i] = 0ULL;
    if (blockIdx.x == 0) {
        const long long* p = (const long long*)ei;
        int t = threadIdx.x;
        int bad = 0;
        #pragma unroll
        for (int k = 0; k < 4; k++) {
            int s = t + k * 256;
            long long v = p[((long long)s * 6247) % N_EDGES];
            if (v < 0 || v >= N_NODES) bad = 1;
        }
        int any_bad = __syncthreads_or(bad);
        if (t == 0) g_is64 = any_bad ? 0 : 1;
    }
}

__device__ __forceinline__ int load_ei(const void* ei, long long pos, int is64) {
    return is64 ? (int)((const long long*)ei)[pos] : ((const int*)ei)[pos];
}

// ---------------- fused count+degree+bucket fill ----------------
__global__ void fill_k(const void* __restrict__ ei,
                       const float* __restrict__ w) {
    int e = blockIdx.x * blockDim.x + threadIdx.x;
    if (e >= N_EDGES) return;
    int is64 = g_is64;
    int r = load_ei(ei, e, is64);
    int c = load_ei(ei, (long long)N_EDGES + e, is64);
    float wv = w[e];
    unsigned long long pack = (1ULL << CNT_SHIFT) |
        (unsigned long long)(unsigned int)__float2uint_rn(wv * FIX_SCALE);
    unsigned long long old = atomicAdd(&g_cd[c], pack);
    int slot = (int)(old >> CNT_SHIFT);
    g_edge[(size_t)c * STRIDE + slot] = make_int2(r, __float_as_int(wv));
}

// ---------------- layer 1 GEMM: g_hh = half(dinv * (z @ W1)) ---------------
__global__ void __launch_bounds__(128) gemm1_k(const float* __restrict__ z,
                                               const float* __restrict__ W1) {
    __shared__ float Ws[IN_DIM * HID];
    __shared__ float zt[128][33];

    int tid = threadIdx.x;
    int row0 = blockIdx.x * 128;
    for (int i = tid; i < IN_DIM * HID; i += 128) Ws[i] = W1[i];

    float acc[HID];
    #pragma unroll
    for (int c = 0; c < HID; c++) acc[c] = 0.0f;

    for (int k0 = 0; k0 < IN_DIM; k0 += 32) {
        __syncthreads();
        #pragma unroll
        for (int idx = tid; idx < 128 * 32; idx += 128) {
            int r = idx >> 5, kk = idx & 31;
            int gr = row0 + r;
            zt[r][kk] = (gr < N_NODES) ? z[(size_t)gr * IN_DIM + k0 + kk] : 0.0f;
        }
        __syncthreads();
        #pragma unroll
        for (int kk = 0; kk < 32; kk++) {
            float zv = zt[tid][kk];
            const float* wrow = &Ws[(k0 + kk) * HID];
            #pragma unroll
            for (int c = 0; c < HID; c++) acc[c] = fmaf(zv, wrow[c], acc[c]);
        }
    }
    int row = row0 + tid;
    if (row < N_NODES) {
        float di = unpack_dinv(g_cd[row]);
        __half2 hv[HID/2];
        #pragma unroll
        for (int j = 0; j < HID/2; j++)
            hv[j] = __floats2half2_rn(di * acc[2*j], di * acc[2*j+1]);
        float4* hp = (float4*)(g_hh + (size_t)row * (HID/2));
        hp[0] = *(float4*)&hv[0];
        hp[1] = *(float4*)&hv[4];
    }
}

// ---------------- aggregation: pure gather (fp16 src, fp32 acc) -------------
// 8 lanes per node, each lane owns 2 features (one half2). Block 256 = 32 nodes.
__global__ void __launch_bounds__(256) agg_k() {
    int tid  = threadIdx.x;
    int node = blockIdx.x * 32 + (tid >> 3);
    int lane = tid & 7;
    if (node >= N_NODES) return;

    unsigned long long pk = g_cd[node];
    int end = (int)(pk >> CNT_SHIFT);
    float di = unpack_dinv(pk);

    float2 sv = __half22float2(g_hh[(size_t)node * 8 + lane]);   // self term
    float ax = sv.x, ay = sv.y;

    const int2* bucket = g_edge + (size_t)node * STRIDE;
    int k = 0;
    for (; k + 4 <= end; k += 4) {
        int2 e0 = __ldg(bucket + k + 0);
        int2 e1 = __ldg(bucket + k + 1);
        int2 e2 = __ldg(bucket + k + 2);
        int2 e3 = __ldg(bucket + k + 3);
        float2 h0 = __half22float2(g_hh[(size_t)e0.x * 8 + lane]);
        float2 h1 = __half22float2(g_hh[(size_t)e1.x * 8 + lane]);
        float2 h2 = __half22float2(g_hh[(size_t)e2.x * 8 + lane]);
        float2 h3 = __half22float2(g_hh[(size_t)e3.x * 8 + lane]);
        float w0 = __int_as_float(e0.y), w1 = __int_as_float(e1.y);
        float w2 = __int_as_float(e2.y), w3 = __int_as_float(e3.y);
        ax = fmaf(w0, h0.x, ax); ay = fmaf(w0, h0.y, ay);
        ax = fmaf(w1, h1.x, ax); ay = fmaf(w1, h1.y, ay);
        ax = fmaf(w2, h2.x, ax); ay = fmaf(w2, h2.y, ay);
        ax = fmaf(w3, h3.x, ax); ay = fmaf(w3, h3.y, ay);
    }
    for (; k < end; k++) {
        int2 e = __ldg(bucket + k);
        float2 h = __half22float2(g_hh[(size_t)e.x * 8 + lane]);
        float wv = __int_as_float(e.y);
        ax = fmaf(wv, h.x, ax); ay = fmaf(wv, h.y, ay);
    }
    float2* xp = (float2*)(g_x + (size_t)node * HID + 2 * lane);
    *xp = make_float2(di * ax, di * ay);
}

// ---------------- layer 2: g_hh = half(dinv * (relu(g_x + b1) @ W2)) --------
__global__ void gemm2_k(const float* __restrict__ W2,
                        const float* __restrict__ b1) {
    __shared__ float Ws[HID * HID];
    __shared__ float bs[HID];
    int tid = threadIdx.x;
    if (tid < HID * HID) Ws[tid] = W2[tid];
    if (tid < HID) bs[tid] = b1[tid];
    __syncthreads();

    int i = blockIdx.x * blockDim.x + tid;
    if (i >= N_NODES) return;

    float v[HID];
    const float4* xp = (const float4*)(g_x + (size_t)i * HID);
    #pragma unroll
    for (int j = 0; j < 4; j++) {
        float4 t = xp[j];
        v[j*4+0] = t.x; v[j*4+1] = t.y; v[j*4+2] = t.z; v[j*4+3] = t.w;
    }
    #pragma unroll
    for (int kk = 0; kk < HID; kk++) v[kk] = fmaxf(v[kk] + bs[kk], 0.0f);

    float acc[HID];
    #pragma unroll
    for (int c = 0; c < HID; c++) acc[c] = 0.0f;
    #pragma unroll
    for (int kk = 0; kk < HID; kk++) {
        #pragma unroll
        for (int c = 0; c < HID; c++) acc[c] = fmaf(v[kk], Ws[kk * HID + c], acc[c]);
    }
    float di = unpack_dinv(g_cd[i]);
    __half2 hv[HID/2];
    #pragma unroll
    for (int j = 0; j < HID/2; j++)
        hv[j] = __floats2half2_rn(di * acc[2*j], di * acc[2*j+1]);
    float4* hp = (float4*)(g_hh + (size_t)i * (HID/2));
    hp[0] = *(float4*)&hv[0];
    hp[1] = *(float4*)&hv[4];
}

// ---------------- classifier + bias2 + log_softmax ----------------
__global__ void __launch_bounds__(128) cls_k(const float* __restrict__ b2,
                                             const float* __restrict__ Wc,
                                             const float* __restrict__ bc,
                                             float* __restrict__ out) {
    __shared__ float Ws[HID * CLASSES];
    __shared__ float bcs[CLASSES];
    __shared__ float b2s[HID];
    int tid = threadIdx.x;
    for (int i = tid; i < HID * CLASSES; i += 128) Ws[i] = Wc[i];
    if (tid < CLASSES) bcs[tid] = bc[tid];
    if (tid < HID) b2s[tid] = b2[tid];
    __syncthreads();

    int i = blockIdx.x * 128 + tid;
    if (i >= N_NODES) return;

    float v[HID];
    const float4* xp = (const float4*)(g_x + (size_t)i * HID);
    #pragma unroll
    for (int j = 0; j < 4; j++) {
        float4 t = xp[j];
        v[j*4+0] = t.x; v[j*4+1] = t.y; v[j*4+2] = t.z; v[j*4+3] = t.w;
    }
    #pragma unroll
    for (int kk = 0; kk < HID; kk++) v[kk] += b2s[kk];

    float lg[CLASSES];
    #pragma unroll
    for (int j = 0; j < CLASSES; j++) lg[j] = bcs[j];
    #pragma unroll
    for (int kk = 0; kk < HID; kk++) {
        float vk = v[kk];
        #pragma unroll
        for (int j = 0; j < CLASSES; j++) lg[j] = fmaf(vk, Ws[kk * CLASSES + j], lg[j]);
    }

    float mx = lg[0];
    #pragma unroll
    for (int j = 1; j < CLASSES; j++) mx = fmaxf(mx, lg[j]);
    float se = 0.0f;
    #pragma unroll
    for (int j = 0; j < CLASSES; j++) se += __expf(lg[j] - mx);
    float lse = mx + __logf(se);

    float4* op = (float4*)(out + (size_t)i * CLASSES);
    #pragma unroll
    for (int j = 0; j < CLASSES / 4; j++)
        op[j] = make_float4(lg[j*4+0] - lse, lg[j*4+1] - lse,
                            lg[j*4+2] - lse, lg[j*4+3] - lse);
}

// ---------------- launcher ----------------
extern "C" void kernel_launch(void* const* d_in, const int* in_sizes, int n_in,
                              void* d_out, int out_size) {
    const float* z  = (const float*)d_in[0];
    const void*  ei = d_in[1];
    const float* w  = (const float*)d_in[2];
    const float* W1 = (const float*)d_in[3];
    const float* b1 = (const float*)d_in[4];
    const float* W2 = (const float*)d_in[5];
    const float* b2 = (const float*)d_in[6];
    const float* Wc = (const float*)d_in[7];
    const float* bc = (const float*)d_in[8];
    float* out = (float*)d_out;

    const int TB = 256;
    int nb_n = (N_NODES + TB - 1) / TB;
    int nb_e = (N_EDGES + TB - 1) / TB;
    int nb_g = (N_NODES + 127) / 128;
    int nb_a = (N_NODES + 31) / 32;

    init_k<<<nb_n, TB>>>(ei);
    fill_k<<<nb_e, TB>>>(ei, w);

    gemm1_k<<<nb_g, 128>>>(z, W1);     // dinv + fp16 conversion in epilogue
    agg_k<<<nb_a, 256>>>();

    gemm2_k<<<nb_n, TB>>>(W2, b1);
    agg_k<<<nb_a, 256>>>();

    cls_k<<<nb_g, 128>>>(b2, Wc, bc, out);
}